// round 7
// baseline (speedup 1.0000x reference)
#include <cuda_runtime.h>
#include <cuda_bf16.h>
#include <math.h>
#include <stdint.h>

#define B_    64
#define CIN_  256
#define HID_  256
#define COUT_ 10
#define EPS_  1e-5f

// ---------------------------------------------------------------------------
// Device globals (no runtime allocation allowed)
// ---------------------------------------------------------------------------
__device__ float g_kfeat[B_ * HID_ * 25];        // (64,256,5,5)
__device__ float g_sfeat[B_ * HID_ * 841];       // (64,256,29,29)
__device__ float g_h    [B_ * HID_ * 625];       // (64,256,25,25)
// packed bf16 hi/lo weights, smem-ready order
__device__ __align__(16) uint32_t g_wk_hi[9 * 256 * 128], g_wk_lo[9 * 256 * 128];
__device__ __align__(16) uint32_t g_ws_hi[9 * 256 * 128], g_ws_lo[9 * 256 * 128];
__device__ __align__(16) uint32_t g_wd_hi[256 * 384],     g_wd_lo[256 * 384];
__device__ __align__(16) uint32_t g_wh1_hi[256 * 128],    g_wh1_lo[256 * 128];
// packed bf16 hi/lo inputs: [icpair 128][b 64][HW]
__device__ __align__(16) uint32_t g_kin_hi[128 * 64 * 49],  g_kin_lo[128 * 64 * 49];
__device__ __align__(16) uint32_t g_sin_hi[128 * 64 * 961], g_sin_lo[128 * 64 * 961];
// packed bf16 hi/lo activations: [kpair][n=40000]
__device__ __align__(16) uint32_t g_featP_hi[384 * 40000], g_featP_lo[384 * 40000];
__device__ __align__(16) uint32_t g_f2P_hi [128 * 40000], g_f2P_lo [128 * 40000];

// ---------------------------------------------------------------------------
// PTX helpers (baseline ISA only; compiles for plain compute_103)
// ---------------------------------------------------------------------------
__device__ __forceinline__ void mma_bf16(float* c, const uint32_t* a,
                                         const uint32_t* b) {
    asm volatile(
        "mma.sync.aligned.m16n8k16.row.col.f32.bf16.bf16.f32 "
        "{%0,%1,%2,%3}, {%4,%5,%6,%7}, {%8,%9}, {%0,%1,%2,%3};"
        : "+f"(c[0]), "+f"(c[1]), "+f"(c[2]), "+f"(c[3])
        : "r"(a[0]), "r"(a[1]), "r"(a[2]), "r"(a[3]), "r"(b[0]), "r"(b[1]));
}

__device__ __forceinline__ void ldm4(uint32_t* d, uint32_t addr) {
    asm volatile("ldmatrix.sync.aligned.m8n8.x4.shared.b16 {%0,%1,%2,%3}, [%4];"
                 : "=r"(d[0]), "=r"(d[1]), "=r"(d[2]), "=r"(d[3]) : "r"(addr));
}

__device__ __forceinline__ uint32_t smem_u32(const void* p) {
    uint32_t a;
    asm("{ .reg .u64 t; cvta.to.shared.u64 t, %1; cvt.u32.u64 %0, t; }"
        : "=r"(a) : "l"(p));
    return a;
}

#define CP_ASYNC16(dst, src) \
    asm volatile("cp.async.cg.shared.global [%0], [%1], 16;" :: "r"(dst), "l"(src))
#define CP_COMMIT()  asm volatile("cp.async.commit_group;")
#define CP_WAIT0()   asm volatile("cp.async.wait_group 0;" ::: "memory")

__device__ __forceinline__ void split2(float a, float b, uint32_t& hi, uint32_t& lo) {
    __nv_bfloat162 h = __floats2bfloat162_rn(a, b);
    hi = *reinterpret_cast<uint32_t*>(&h);
    float ra = a - __bfloat162float(h.x);
    float rb = b - __bfloat162float(h.y);
    __nv_bfloat162 l = __floats2bfloat162_rn(ra, rb);
    lo = *reinterpret_cast<uint32_t*>(&l);
}

__device__ __forceinline__ void split1_u16(float v, uint16_t& hi, uint16_t& lo) {
    __nv_bfloat16 h = __float2bfloat16_rn(v);
    hi = *reinterpret_cast<uint16_t*>(&h);
    float r = v - __bfloat162float(h);
    __nv_bfloat16 l = __float2bfloat16_rn(r);
    lo = *reinterpret_cast<uint16_t*>(&l);
}

// ---------------------------------------------------------------------------
// Prep kernels
// ---------------------------------------------------------------------------
__global__ void prep_w3(const float* __restrict__ w,
                        uint32_t* __restrict__ oh, uint32_t* __restrict__ ol) {
    int idx = blockIdx.x * 256 + threadIdx.x;
    if (idx >= 9 * 256 * 128) return;
    int tap = idx >> 15;
    int rem = idx & 32767;
    int oc = rem >> 7, p = rem & 127;
    float a = w[(size_t)oc * 2304 + (2 * p) * 9 + tap];
    float b = w[(size_t)oc * 2304 + (2 * p + 1) * 9 + tap];
    split2(a, b, oh[idx], ol[idx]);
}

template <int K>
__global__ void prep_w1(const float* __restrict__ w,
                        uint32_t* __restrict__ oh, uint32_t* __restrict__ ol) {
    int idx = blockIdx.x * 256 + threadIdx.x;
    if (idx >= 256 * (K / 2)) return;
    int oc = idx / (K / 2), kp = idx - oc * (K / 2);
    split2(w[(size_t)oc * K + 2 * kp], w[(size_t)oc * K + 2 * kp + 1],
           oh[idx], ol[idx]);
}

template <int HW>
__global__ void prep_in(const float* __restrict__ in,
                        uint32_t* __restrict__ oh, uint32_t* __restrict__ ol) {
    int idx = blockIdx.x * 256 + threadIdx.x;
    if (idx >= 128 * 64 * HW) return;
    int p = idx / (64 * HW);
    int rem = idx - p * (64 * HW);
    int b = rem / HW, pix = rem - b * HW;
    const float* src = in + (size_t)b * 256 * HW + (2 * p) * HW + pix;
    split2(src[0], src[HW], oh[idx], ol[idx]);
}

// ---------------------------------------------------------------------------
// Tensor-core GEMM (bf16x3): C[oc][n] = sum_k A[oc][k]*B[k][n], + BN (+ReLU)
// MODE 0: implicit-GEMM 3x3 conv (k = tap*256+ic). MODE 1: 1x1 conv.
// EPI 0: fp32 NCHW. EPI 1: packed bf16 hi/lo [kpair][n].
// Tile M=128 x N=128 x K=32/stage; double-buffered; A cp.async issued EARLY
// (right after the stage barrier) so its latency hides behind the mma burst.
// RSTR = 20 words (80 B rows): 16-byte aligned for STS.128 / cp.async.16.
// ---------------------------------------------------------------------------
template <int MODE, int HIN, int WIN, int KT, bool RELU, int EPI>
__global__ void __launch_bounds__(256, 2)
gemm_mma2_kernel(const uint32_t* __restrict__ bH_src, const uint32_t* __restrict__ bL_src,
                 const uint32_t* __restrict__ aH_src, const uint32_t* __restrict__ aL_src,
                 const float* __restrict__ bn, float* __restrict__ out,
                 uint16_t* __restrict__ outH, uint16_t* __restrict__ outL) {
    constexpr int WOUT = WIN - 2;
    constexpr int PXB  = (MODE == 0) ? (HIN - 2) * WOUT : 625;
    constexpr int NP   = 64 * PXB;
    constexpr int HW   = HIN * WIN;
    constexpr int S    = KT / 32;
    constexpr int RSTR = 20;
    constexpr int TILE = 128 * RSTR;
    constexpr int AR   = (MODE == 0) ? 128 : (KT / 2);
    constexpr int PLSTR = 64 * HW;

    extern __shared__ uint32_t smem[];
    const uint32_t smb = smem_u32(smem);

    const int tid  = threadIdx.x;
    const int warp = tid >> 5;
    const int lane = tid & 31;
    const int gid  = lane >> 2;
    const int tig  = lane & 3;
    const int moff = (warp >> 1) * 32;
    const int noff = (warp & 1) * 64;

    const int oc0 = blockIdx.y * 128;
    const int p0  = blockIdx.x * 128;

    const int aRow = lane & 15;
    const int aCol = (lane >> 4) * 4;
    const int bRow = (lane & 7) + ((lane >> 4) & 1) * 8;
    const int bCol = ((lane >> 3) & 1) * 4;

    const int nloc  = tid & 127;
    const int nglob = p0 + nloc;
    const bool nvalid = (nglob < NP);
    int bbase = 0;
    if (MODE == 0) {
        int nn = nvalid ? nglob : 0;
        int b = nn / PXB; int rem = nn - b * PXB;
        int y = rem / WOUT; int x = rem - y * WOUT;
        bbase = b * HW + y * WIN + x;
    }

    float acc[2][8][4];
#pragma unroll
    for (int a = 0; a < 2; a++)
#pragma unroll
        for (int b = 0; b < 8; b++)
#pragma unroll
            for (int c = 0; c < 4; c++) acc[a][b][c] = 0.f;

    auto prefetchB = [&](int s, uint32_t v[4][4]) {
        int tapoff = 0, plane0 = 0;
        if (MODE == 0) {
            int tap = s >> 3; plane0 = (s & 7) * 16;
            tapoff = (tap / 3) * WIN + (tap % 3);
        }
#pragma unroll
        for (int i = 0; i < 4; i++) {
            int task = tid + 256 * i;
            int hl = task >> 9;
            int wg = (task >> 7) & 3;
            const uint32_t* src = hl ? bL_src : bH_src;
#pragma unroll
            for (int j = 0; j < 4; j++) {
                int w = wg * 4 + j;
                long addr = (MODE == 0)
                    ? (long)(plane0 + w) * PLSTR + bbase + tapoff
                    : (long)(s * 16 + w) * 40000 + nglob;
                v[i][j] = nvalid ? __ldg(src + addr) : 0u;
            }
        }
    };
    auto storeB = [&](int buf, uint32_t v[4][4]) {
#pragma unroll
        for (int i = 0; i < 4; i++) {
            int task = tid + 256 * i;
            int hl = task >> 9;
            int wg = (task >> 7) & 3;
            uint32_t* dst = &smem[(buf * 4 + 2 + hl) * TILE + nloc * RSTR + wg * 4];
            *reinterpret_cast<uint4*>(dst) =
                make_uint4(v[i][0], v[i][1], v[i][2], v[i][3]);
        }
    };
    auto stageA = [&](int buf, int s) {
        int abase;
        if (MODE == 0) {
            int tap = s >> 3; int plane0 = (s & 7) * 16;
            abase = tap * 32768 + oc0 * 128 + plane0;
        } else {
            abase = oc0 * (KT / 2) + s * 16;
        }
#pragma unroll
        for (int i = 0; i < 4; i++) {
            int task = tid + 256 * i;
            int hl = task >> 9;
            int rem = task & 511;
            int r = rem >> 2;
            int c = (rem & 3) * 4;
            const uint32_t* src = (hl ? aL_src : aH_src) + abase + r * AR + c;
            uint32_t dst = smb + ((buf * 4 + hl) * TILE + r * RSTR + c) * 4;
            CP_ASYNC16(dst, src);
        }
    };

    // prologue: fill buf 0
    {
        uint32_t v[4][4];
        prefetchB(0, v);
        storeB(0, v);
        stageA(0, 0);
        CP_COMMIT();
    }

    for (int s = 0; s < S; s++) {
        const int buf = s & 1;
        CP_WAIT0();
        __syncthreads();

        const bool have = (s + 1 < S);
        // EARLY: issue next A tile immediately (buf^1 is dead since last barrier)
        if (have) {
            stageA(buf ^ 1, s + 1);
            CP_COMMIT();
        }
        uint32_t vpre[4][4];
        if (have) prefetchB(s + 1, vpre);

        const uint32_t smA_hi = smb + (buf * 4 + 0) * TILE * 4;
        const uint32_t smA_lo = smb + (buf * 4 + 1) * TILE * 4;
        const uint32_t smB_hi = smb + (buf * 4 + 2) * TILE * 4;
        const uint32_t smB_lo = smb + (buf * 4 + 3) * TILE * 4;
#pragma unroll
        for (int kc = 0; kc < 2; kc++) {
            uint32_t aH[2][4], aL[2][4];
#pragma unroll
            for (int mf = 0; mf < 2; mf++) {
                uint32_t off = ((moff + mf * 16 + aRow) * RSTR + kc * 8 + aCol) * 4;
                ldm4(aH[mf], smA_hi + off);
                ldm4(aL[mf], smA_lo + off);
            }
#pragma unroll
            for (int nfp = 0; nfp < 4; nfp++) {
                uint32_t boff = ((noff + nfp * 16 + bRow) * RSTR + kc * 8 + bCol) * 4;
                uint32_t bHf[4], bLf[4];
                ldm4(bHf, smB_hi + boff);
                ldm4(bLf, smB_lo + boff);
#pragma unroll
                for (int snf = 0; snf < 2; snf++) {
                    int nf = nfp * 2 + snf;
#pragma unroll
                    for (int mf = 0; mf < 2; mf++) {
                        mma_bf16(acc[mf][nf], aH[mf], &bHf[2 * snf]);
                        mma_bf16(acc[mf][nf], aH[mf], &bLf[2 * snf]);
                        mma_bf16(acc[mf][nf], aL[mf], &bHf[2 * snf]);
                    }
                }
            }
        }

        if (have) storeB(buf ^ 1, vpre);
    }

    // epilogue
    __syncthreads();
    float* Cs = (float*)smem;                // 128 x 132 fp32 (67584 B)
#pragma unroll
    for (int mf = 0; mf < 2; mf++) {
#pragma unroll
        for (int nf = 0; nf < 8; nf++) {
            int m0 = moff + mf * 16 + gid;
            int nl = noff + nf * 8 + 2 * tig;
            *(float2*)&Cs[m0 * 132 + nl]       = make_float2(acc[mf][nf][0], acc[mf][nf][1]);
            *(float2*)&Cs[(m0 + 8) * 132 + nl] = make_float2(acc[mf][nf][2], acc[mf][nf][3]);
        }
    }
    __syncthreads();

    for (int t = warp; t < 128; t += 8) {
        const int oc = oc0 + t;
        const float g  = bn[oc];
        const float be = bn[256 + oc];
        const float mm = bn[512 + oc];
        const float vv = bn[768 + oc];
        const float inv  = g * rsqrtf(vv + EPS_);
        const float bias = be - mm * inv;
#pragma unroll
        for (int cc0 = 0; cc0 < 128; cc0 += 32) {
            int cc = cc0 + lane;
            int n = p0 + cc;
            if (n < NP) {
                float val = Cs[t * 132 + cc] * inv + bias;
                if (RELU) val = fmaxf(val, 0.f);
                if (EPI == 0) {
                    int b = n / PXB; int rq = n - b * PXB;
                    out[((size_t)(b * 256 + oc)) * PXB + rq] = val;
                } else {
                    uint16_t h, l;
                    split1_u16(val, h, l);
                    size_t off = (size_t)(oc >> 1) * 80000 + n * 2 + (oc & 1);
                    outH[off] = h;
                    outL[off] = l;
                }
            }
        }
    }
}

// ---------------------------------------------------------------------------
// Multi-scale depthwise xcorr; emits packed bf16 hi/lo [kpair][n] directly.
// ---------------------------------------------------------------------------
__global__ void multixcorr_kernel(const float* __restrict__ s,
                                  const float* __restrict__ k,
                                  uint32_t* __restrict__ fh,
                                  uint32_t* __restrict__ fl) {
    const int c = blockIdx.x;
    const int b = blockIdx.y;

    __shared__ float ss[29 * 29];
    __shared__ float kk[25];

    const float* sp = s + ((size_t)b * HID_ + c) * 841;
    const float* kp = k + ((size_t)b * HID_ + c) * 25;

    for (int i = threadIdx.x; i < 841; i += blockDim.x) ss[i] = sp[i];
    if (threadIdx.x < 25) kk[threadIdx.x] = kp[threadIdx.x];
    __syncthreads();

    uint16_t* fH = (uint16_t*)fh;
    uint16_t* fL = (uint16_t*)fl;
    const int half = c & 1;
    const int kp0 = c >> 1;

    for (int p = threadIdx.x; p < 625; p += blockDim.x) {
        const int y = p / 25, x = p - (p / 25) * 25;
        float s_full = 0.f, s_in = 0.f;
#pragma unroll
        for (int dy = 0; dy < 5; dy++)
#pragma unroll
            for (int dx = 0; dx < 5; dx++) {
                float vv = ss[(y + dy) * 29 + (x + dx)] * kk[dy * 5 + dx];
                s_full += vv;
                if (dy >= 1 && dy <= 3 && dx >= 1 && dx <= 3) s_in += vv;
            }
        float s_c = ss[(y + 2) * 29 + (x + 2)] * kk[12];
        const int n = b * 625 + p;
        uint16_t h, l;
        split1_u16(s_full, h, l);
        fH[(size_t)kp0 * 80000 + n * 2 + half] = h;
        fL[(size_t)kp0 * 80000 + n * 2 + half] = l;
        split1_u16(s_in, h, l);
        fH[(size_t)(128 + kp0) * 80000 + n * 2 + half] = h;
        fL[(size_t)(128 + kp0) * 80000 + n * 2 + half] = l;
        split1_u16(s_c, h, l);
        fH[(size_t)(256 + kp0) * 80000 + n * 2 + half] = h;
        fL[(size_t)(256 + kp0) * 80000 + n * 2 + half] = l;
    }
}

// ---------------------------------------------------------------------------
// Final 1x1: (B,256,625) x (10,256) + bias -> (B,10,625). grid (B, 5).
// ---------------------------------------------------------------------------
__global__ void conv1x1_out_kernel(const float* __restrict__ in,
                                   const float* __restrict__ w,
                                   const float* __restrict__ bias,
                                   float* __restrict__ out) {
    const int b = blockIdx.x;
    const int chunk = blockIdx.y;

    __shared__ float wsm[COUT_ * HID_];
    for (int i = threadIdx.x; i < COUT_ * HID_; i += blockDim.x) wsm[i] = w[i];
    __syncthreads();

    const float* ib = in + (size_t)b * HID_ * 625;
    float* ob = out + (size_t)b * COUT_ * 625;

    const int pend = min(625, (chunk + 1) * 125);
    for (int p = chunk * 125 + threadIdx.x; p < pend; p += blockDim.x) {
        float acc[COUT_];
#pragma unroll
        for (int o = 0; o < COUT_; o++) acc[o] = bias[o];
        for (int c = 0; c < HID_; c++) {
            float vv = ib[(size_t)c * 625 + p];
#pragma unroll
            for (int o = 0; o < COUT_; o++) acc[o] = fmaf(vv, wsm[o * HID_ + c], acc[o]);
        }
#pragma unroll
        for (int o = 0; o < COUT_; o++) ob[(size_t)o * 625 + p] = acc[o];
    }
}

// ---------------------------------------------------------------------------
extern "C" void kernel_launch(void* const* d_in, const int* in_sizes, int n_in,
                              void* d_out, int out_size) {
    const float* kernel_in = (const float*)d_in[0];
    const float* search_in = (const float*)d_in[1];
    const float* wk  = (const float*)d_in[2];
    const float* bnk = (const float*)d_in[3];
    const float* ws  = (const float*)d_in[4];
    const float* bns = (const float*)d_in[5];
    const float* wd  = (const float*)d_in[6];
    const float* bnd = (const float*)d_in[7];
    const float* wh1 = (const float*)d_in[8];
    const float* bnh = (const float*)d_in[9];
    const float* wh2 = (const float*)d_in[10];
    const float* bh2 = (const float*)d_in[11];
    float* out = (float*)d_out;

    float *kfeat, *sfeat, *h;
    uint32_t *wkh, *wkl, *wsh, *wsl, *wdh, *wdl, *wh1h, *wh1l;
    uint32_t *kinh, *kinl, *sinh, *sinl, *fph, *fpl, *f2h, *f2l;
    cudaGetSymbolAddress((void**)&kfeat, g_kfeat);
    cudaGetSymbolAddress((void**)&sfeat, g_sfeat);
    cudaGetSymbolAddress((void**)&h,     g_h);
    cudaGetSymbolAddress((void**)&wkh, g_wk_hi);  cudaGetSymbolAddress((void**)&wkl, g_wk_lo);
    cudaGetSymbolAddress((void**)&wsh, g_ws_hi);  cudaGetSymbolAddress((void**)&wsl, g_ws_lo);
    cudaGetSymbolAddress((void**)&wdh, g_wd_hi);  cudaGetSymbolAddress((void**)&wdl, g_wd_lo);
    cudaGetSymbolAddress((void**)&wh1h, g_wh1_hi); cudaGetSymbolAddress((void**)&wh1l, g_wh1_lo);
    cudaGetSymbolAddress((void**)&kinh, g_kin_hi); cudaGetSymbolAddress((void**)&kinl, g_kin_lo);
    cudaGetSymbolAddress((void**)&sinh, g_sin_hi); cudaGetSymbolAddress((void**)&sinl, g_sin_lo);
    cudaGetSymbolAddress((void**)&fph, g_featP_hi); cudaGetSymbolAddress((void**)&fpl, g_featP_lo);
    cudaGetSymbolAddress((void**)&f2h, g_f2P_hi);  cudaGetSymbolAddress((void**)&f2l, g_f2P_lo);

    constexpr int SMEM = 8 * 128 * 20 * 4;  // 81920

    cudaFuncSetAttribute(gemm_mma2_kernel<0, 7, 7, 2304, true, 0>,
                         cudaFuncAttributeMaxDynamicSharedMemorySize, SMEM);
    cudaFuncSetAttribute(gemm_mma2_kernel<0, 31, 31, 2304, true, 0>,
                         cudaFuncAttributeMaxDynamicSharedMemorySize, SMEM);
    cudaFuncSetAttribute(gemm_mma2_kernel<1, 3, 3, 768, false, 1>,
                         cudaFuncAttributeMaxDynamicSharedMemorySize, SMEM);
    cudaFuncSetAttribute(gemm_mma2_kernel<1, 3, 3, 256, true, 0>,
                         cudaFuncAttributeMaxDynamicSharedMemorySize, SMEM);

    // Launch order arranged so gemm_s is ncu launch index 5 (-s 5 -c 1 window).
    prep_in<961><<<(128 * 64 * 961 + 255) / 256, 256>>>(search_in, sinh, sinl); // 0
    prep_w3<<<(9 * 256 * 128 + 255) / 256, 256>>>(ws, wsh, wsl);                // 1
    prep_w3<<<(9 * 256 * 128 + 255) / 256, 256>>>(wk, wkh, wkl);                // 2
    prep_w1<768><<<(256 * 384 + 255) / 256, 256>>>(wd, wdh, wdl);               // 3
    prep_w1<256><<<(256 * 128 + 255) / 256, 256>>>(wh1, wh1h, wh1l);            // 4

    // 5) search branch conv3x3 -> g_sfeat ; NP=53824 -> 421 tiles  [PROFILED]
    gemm_mma2_kernel<0, 31, 31, 2304, true, 0><<<dim3(421, 2), 256, SMEM>>>(
        sinh, sinl, wsh, wsl, bns, sfeat, nullptr, nullptr);

    prep_in<49><<<(128 * 64 * 49 + 255) / 256, 256>>>(kernel_in, kinh, kinl);   // 6

    // 7) kernel branch conv3x3 -> g_kfeat ; NP=1600 -> 13 tiles
    gemm_mma2_kernel<0, 7, 7, 2304, true, 0><<<dim3(13, 2), 256, SMEM>>>(
        kinh, kinl, wkh, wkl, bnk, kfeat, nullptr, nullptr);
    // 8) xcorr -> packed featP
    multixcorr_kernel<<<dim3(HID_, B_), 256>>>(sfeat, kfeat, fph, fpl);
    // 9) wd + bn -> packed f2P
    gemm_mma2_kernel<1, 3, 3, 768, false, 1><<<dim3(313, 2), 256, SMEM>>>(
        fph, fpl, wdh, wdl, bnd, nullptr, (uint16_t*)f2h, (uint16_t*)f2l);
    // 10) wh1 + bn + relu -> g_h
    gemm_mma2_kernel<1, 3, 3, 256, true, 0><<<dim3(313, 2), 256, SMEM>>>(
        f2h, f2l, wh1h, wh1l, bnh, h, nullptr, nullptr);
    // 11) wh2 + bias -> out
    conv1x1_out_kernel<<<dim3(B_, 5), 128>>>(h, wh2, bh2, out);
}